// round 7
// baseline (speedup 1.0000x reference)
#include <cuda_runtime.h>
#include <cstdint>
#include <cstddef>

#define BB 64
#define TT 512
#define EE 256
#define HH 256
#define LLB 9
#define G4 1024   // 4*H

typedef unsigned long long u64;

// Scratch (device globals; no allocations allowed)
// g_xg: float [dir][t][col(1024)][b(64)]   256 MiB
__device__ float g_xg[(size_t)2*TT*G4*BB];
// g_h : float [dir][t][u(256)][b(64)]       64 MiB
__device__ float g_h [(size_t)2*TT*HH*BB];
__device__ int      g_seqlen[BB];
__device__ unsigned g_barc[128];  // 4 counters on separate 128B lines: [0],[32] real; [64],[96] probe

// ---------------- f32x2 helpers ----------------
__device__ __forceinline__ u64 pk2(float x, float y){
    u64 r; asm("mov.b64 %0,{%1,%2};" : "=l"(r) : "f"(x), "f"(y)); return r;
}
__device__ __forceinline__ void upk2(u64 v, float& x, float& y){
    asm("mov.b64 {%0,%1},%2;" : "=f"(x), "=f"(y) : "l"(v));
}
__device__ __forceinline__ u64 fma2(u64 a, u64 b, u64 c){
    u64 d; asm("fma.rn.f32x2 %0,%1,%2,%3;" : "=l"(d) : "l"(a), "l"(b), "l"(c)); return d;
}

// ---------------- release/acquire barrier primitives ----------------
__device__ __forceinline__ void red_release_add1(unsigned* p){
    asm volatile("red.release.gpu.add.u32 [%0],1;" :: "l"(p) : "memory");
}
__device__ __forceinline__ unsigned ld_acquire(const unsigned* p){
    unsigned v; asm volatile("ld.acquire.gpu.u32 %0,[%1];" : "=r"(v) : "l"(p) : "memory");
    return v;
}

__device__ __forceinline__ float sigf(float x){
    return __fdividef(1.f, 1.f + __expf(-x));
}
__device__ __forceinline__ float tanhfast(float x){
    return 1.f - __fdividef(2.f, __expf(2.f*x) + 1.f);
}

// ---------------------------------------------------------------- seq_len
__global__ void k_seqlen(const int* __restrict__ tokens, float* __restrict__ out_seq){
    int b = blockIdx.x, tid = threadIdx.x;
    int cnt = 0;
    for (int t = tid; t < TT; t += blockDim.x)
        cnt += (tokens[b*TT + t] != 0);
    __shared__ int sred[128];
    sred[tid] = cnt; __syncthreads();
    for (int s = 64; s > 0; s >>= 1){
        if (tid < s) sred[tid] += sred[tid+s];
        __syncthreads();
    }
    if (tid == 0){ g_seqlen[b] = sred[0]; out_seq[b] = (float)sred[0]; }
}

__global__ void k_init(){
    if (threadIdx.x < 128) g_barc[threadIdx.x] = 0u;
}

// ---------------------------------------------------------------- xg GEMM (identical to R6)
__global__ void __launch_bounds__(128) k_xg(
    const int* __restrict__ tokens, const float* __restrict__ emb,
    const float* __restrict__ Wxf, const float* __restrict__ bf,
    const float* __restrict__ Wxb, const float* __restrict__ bb_)
{
    extern __shared__ float smf[];
    float* As = smf;                   // [256 k][64 b]        64KB
    u64*   Wd = (u64*)(smf + 16384);   // [256 k][64 c] dup   128KB
    __shared__ int toks[64];

    int t    = blockIdx.x;
    int ct   = blockIdx.y;
    int dir  = ct >> 4;
    int col0 = (ct & 15) * 64;
    const float* Wx   = dir ? Wxb : Wxf;
    const float* bias = dir ? bb_ : bf;
    int tid  = threadIdx.x;
    int w    = tid >> 5, lane = tid & 31;
    int c8   = lane >> 4, bq = lane & 15;
    int cc   = w*16 + c8*8;

    if (tid < 64) toks[tid] = tokens[tid*TT + t];
    __syncthreads();

    for (int i = tid; i < 4096; i += 128){
        int k4 = i >> 6, b = i & 63;
        float4 v = *(const float4*)(emb + (size_t)toks[b]*EE + k4*4);
        As[(4*k4+0)*64 + b] = v.x;
        As[(4*k4+1)*64 + b] = v.y;
        As[(4*k4+2)*64 + b] = v.z;
        As[(4*k4+3)*64 + b] = v.w;
    }
    for (int i = tid; i < 4096; i += 128){
        int k = i >> 4, q = i & 15;
        float4 v = *(const float4*)(Wx + (size_t)k*G4 + col0 + q*4);
        Wd[k*64 + q*4 + 0] = pk2(v.x, v.x);
        Wd[k*64 + q*4 + 1] = pk2(v.y, v.y);
        Wd[k*64 + q*4 + 2] = pk2(v.z, v.z);
        Wd[k*64 + q*4 + 3] = pk2(v.w, v.w);
    }
    __syncthreads();

    u64 acc[8][2];
    #pragma unroll
    for (int j = 0; j < 8; ++j){
        float bv = bias[col0 + cc + j];
        acc[j][0] = pk2(bv, bv);
        acc[j][1] = acc[j][0];
    }

    #pragma unroll 4
    for (int k = 0; k < 256; ++k){
        ulonglong2 a = *(const ulonglong2*)(As + k*64 + 4*bq);
        const u64* wr = Wd + k*64 + cc;
        ulonglong2 w01 = *(const ulonglong2*)(wr);
        ulonglong2 w23 = *(const ulonglong2*)(wr + 2);
        ulonglong2 w45 = *(const ulonglong2*)(wr + 4);
        ulonglong2 w67 = *(const ulonglong2*)(wr + 6);
        acc[0][0]=fma2(a.x,w01.x,acc[0][0]); acc[0][1]=fma2(a.y,w01.x,acc[0][1]);
        acc[1][0]=fma2(a.x,w01.y,acc[1][0]); acc[1][1]=fma2(a.y,w01.y,acc[1][1]);
        acc[2][0]=fma2(a.x,w23.x,acc[2][0]); acc[2][1]=fma2(a.y,w23.x,acc[2][1]);
        acc[3][0]=fma2(a.x,w23.y,acc[3][0]); acc[3][1]=fma2(a.y,w23.y,acc[3][1]);
        acc[4][0]=fma2(a.x,w45.x,acc[4][0]); acc[4][1]=fma2(a.y,w45.x,acc[4][1]);
        acc[5][0]=fma2(a.x,w45.y,acc[5][0]); acc[5][1]=fma2(a.y,w45.y,acc[5][1]);
        acc[6][0]=fma2(a.x,w67.x,acc[6][0]); acc[6][1]=fma2(a.y,w67.x,acc[6][1]);
        acc[7][0]=fma2(a.x,w67.y,acc[7][0]); acc[7][1]=fma2(a.y,w67.y,acc[7][1]);
    }

    float* dst = g_xg + ((size_t)(dir*TT + t)*G4 + col0 + cc)*64 + 4*bq;
    #pragma unroll
    for (int j = 0; j < 8; ++j){
        ulonglong2 v; v.x = acc[j][0]; v.y = acc[j][1];
        *(ulonglong2*)(dst + (size_t)j*64) = v;
    }
}

// ---------------------------------------------------------------- recurrence (templated)
// NSTEPS: number of timesteps to run; COFF: barrier counter bank offset.
// Probe instance (NSTEPS=128, COFF=64) computes a deterministic prefix of g_h
// that the full instance (NSTEPS=512, COFF=0) recomputes identically.
template<int NSTEPS, int COFF>
__global__ void __launch_bounds__(128) k_recur_t(
    const float* __restrict__ Whf, const float* __restrict__ Whb)
{
    extern __shared__ u64 smu[];
    u64* hs = smu;          // [256 k][32 bp]  64KB
    u64* wd = smu + 8192;   // [256 k][4 ul][4 g] dup  32KB

    int cta = blockIdx.x;
    int dir = cta >> 6;
    int u0  = (cta & 63) * 4;
    const float* Wh = dir ? Whb : Whf;
    int tid  = threadIdx.x;
    int w    = tid >> 5, lane = tid & 31;
    int uh   = lane >> 4, bp15 = lane & 15;
    int half = w & 1, upair = w >> 1;
    int ul   = upair*2 + uh;
    int u    = u0 + ul;
    int bp   = half*16 + bp15;

    for (int i = tid; i < 4096; i += 128){
        int k = i >> 4, q = i & 15;
        int ulx = q >> 2, g = q & 3;
        float v = Wh[(size_t)k*G4 + g*HH + u0 + ulx];
        wd[k*16 + ulx*4 + g] = pk2(v, v);
    }
    __syncthreads();

    float ca = 0.f, cb = 0.f;
    float* hF = g_h + (size_t)dir * TT * HH * BB;
    const u64* xg = (const u64*)g_xg;
    unsigned* barp = &g_barc[dir*32 + COFF];
    const u64* wbase = wd + ul*4;

    int t0 = dir ? (TT-1) : 0;
    size_t xb = ((size_t)(dir*TT + t0)*G4 + u)*32 + bp;
    u64 x0 = xg[xb];
    u64 x1 = xg[xb +  8192];
    u64 x2 = xg[xb + 16384];
    u64 x3 = xg[xb + 24576];

    for (int step = 0; step < NSTEPS; ++step){
        int t = dir ? (TT-1-step) : step;
        u64 a0 = x0, a1 = x1, a2 = x2, a3 = x3;

        if (step > 0){
            if (tid == 0){
                unsigned need = 64u * (unsigned)step;
                while (ld_acquire(barp) < need) __nanosleep(32);
            }
            __syncthreads();

            int tp = dir ? (t+1) : (t-1);
            const ulonglong2* src = (const ulonglong2*)(hF + (size_t)tp*HH*BB);
            ulonglong2* dsts = (ulonglong2*)hs;
            #pragma unroll
            for (int i = 0; i < 32; ++i) dsts[tid + 128*i] = src[tid + 128*i];
            __syncthreads();

            #pragma unroll 8
            for (int k = 0; k < 256; ++k){
                u64 h2 = hs[k*32 + bp];
                ulonglong2 w01 = *(const ulonglong2*)(wbase + k*16);
                ulonglong2 w23 = *(const ulonglong2*)(wbase + k*16 + 2);
                a0 = fma2(h2, w01.x, a0);
                a1 = fma2(h2, w01.y, a1);
                a2 = fma2(h2, w23.x, a2);
                a3 = fma2(h2, w23.y, a3);
            }
        }

        float ia, ib, fa, fb, ga, gb, oa, ob;
        upk2(a0, ia, ib);
        upk2(a1, fa, fb);
        upk2(a2, ga, gb);
        upk2(a3, oa, ob);
        ca = sigf(fa)*ca + sigf(ia)*tanhfast(ga);
        cb = sigf(fb)*cb + sigf(ib)*tanhfast(gb);
        float ha = sigf(oa)*tanhfast(ca);
        float hb = sigf(ob)*tanhfast(cb);
        *(u64*)(hF + (size_t)t*HH*BB + (size_t)u*BB + 2*bp) = pk2(ha, hb);

        __syncthreads();
        if (tid == 0) red_release_add1(barp);

        if (step + 1 < NSTEPS){
            int tn = dir ? (t-1) : (t+1);
            size_t xn = ((size_t)(dir*TT + tn)*G4 + u)*32 + bp;
            x0 = xg[xn];
            x1 = xg[xn +  8192];
            x2 = xg[xn + 16384];
            x3 = xg[xn + 24576];
        }
    }
}

// ---------------------------------------------------------------- dense
__global__ void __launch_bounds__(576) k_dense(
    const float* __restrict__ Wd, const float* __restrict__ bd,
    float* __restrict__ out)
{
    extern __shared__ float sm[];
    float* hsf = sm;
    float* Wds = sm + 32768;

    int t = blockIdx.x, tid = threadIdx.x;
    const float4* s0 = (const float4*)(g_h + (size_t)t*HH*BB);
    const float4* s1 = (const float4*)(g_h + (size_t)(TT + t)*HH*BB);
    float4* d0 = (float4*)hsf;
    for (int i = tid; i < 4096; i += 576) d0[i] = s0[i];
    for (int i = tid; i < 4096; i += 576) d0[4096 + i] = s1[i];
    for (int i = tid; i < 512*LLB; i += 576) Wds[i] = Wd[i];
    __syncthreads();

    int b = tid / LLB;
    int l = tid - b*LLB;
    float acc = bd[l];
    #pragma unroll 4
    for (int k = 0; k < 256; ++k)
        acc += hsf[k*64 + b] * Wds[k*LLB + l];
    #pragma unroll 4
    for (int k = 0; k < 256; ++k)
        acc += hsf[16384 + k*64 + b] * Wds[(256+k)*LLB + l];
    out[((size_t)b*TT + t)*LLB + l] = acc;
}

// ---------------------------------------------------------------- CRF
__global__ void k_crf(const int* __restrict__ labels, const float* __restrict__ trans,
                      const float* __restrict__ logits, float* __restrict__ out_ll)
{
    int b = blockIdx.x;
    int j = threadIdx.x;
    int sl = g_seqlen[b];
    const float* lg = logits + (size_t)b*TT*LLB;
    const int*   tg = labels + (size_t)b*TT;

    float sc = 0.f;
    for (int t = j; t < TT; t += 32){
        if (t < sl){
            sc += lg[t*LLB + tg[t]];
            if (t >= 1) sc += trans[tg[t-1]*LLB + tg[t]];
        }
    }
    #pragma unroll
    for (int o = 16; o > 0; o >>= 1) sc += __shfl_xor_sync(0xffffffffu, sc, o);

    float trj[9];
    if (j < 9){
        #pragma unroll
        for (int i = 0; i < 9; ++i) trj[i] = trans[i*LLB + j];
    }
    float a[9];
    #pragma unroll
    for (int i = 0; i < 9; ++i) a[i] = lg[i];

    __shared__ float sa[9];
    int tmax = (sl < TT) ? sl : TT;
    for (int t = 1; t < tmax; ++t){
        if (j < 9){
            float lgt = lg[t*LLB + j];
            float v[9]; float m = -1e30f;
            #pragma unroll
            for (int i = 0; i < 9; ++i){ v[i] = a[i] + trj[i]; m = fmaxf(m, v[i]); }
            float s = 0.f;
            #pragma unroll
            for (int i = 0; i < 9; ++i) s += __expf(v[i] - m);
            sa[j] = m + __logf(s) + lgt;
        }
        __syncwarp();
        #pragma unroll
        for (int i = 0; i < 9; ++i) a[i] = sa[i];
        __syncwarp();
    }

    if (j == 0){
        float m = a[0];
        #pragma unroll
        for (int i = 1; i < 9; ++i) m = fmaxf(m, a[i]);
        float s = 0.f;
        #pragma unroll
        for (int i = 0; i < 9; ++i) s += __expf(a[i] - m);
        out_ll[b] = sc - (m + __logf(s));
    }
}

// ---------------------------------------------------------------- launch
extern "C" void kernel_launch(void* const* d_in, const int* in_sizes, int n_in,
                              void* d_out, int out_size)
{
    const int*   tokens = (const int*)  d_in[0];
    const int*   labels = (const int*)  d_in[1];
    const float* emb    = (const float*)d_in[2];
    const float* Wxf    = (const float*)d_in[3];
    const float* Whf    = (const float*)d_in[4];
    const float* bf     = (const float*)d_in[5];
    const float* Wxb    = (const float*)d_in[6];
    const float* Whb    = (const float*)d_in[7];
    const float* bb     = (const float*)d_in[8];
    const float* Wd     = (const float*)d_in[9];
    const float* bd     = (const float*)d_in[10];
    const float* trans  = (const float*)d_in[11];
    float* out = (float*)d_out;

    cudaFuncSetAttribute(k_xg, cudaFuncAttributeMaxDynamicSharedMemorySize, 196608);
    cudaFuncSetAttribute(k_recur_t<128,64>, cudaFuncAttributeMaxDynamicSharedMemorySize, 98304);
    cudaFuncSetAttribute(k_recur_t<512,0>,  cudaFuncAttributeMaxDynamicSharedMemorySize, 98304);
    cudaFuncSetAttribute(k_dense, cudaFuncAttributeMaxDynamicSharedMemorySize, 149504);

    const int LOGITS_N = BB*TT*LLB;   // 294912

    k_init<<<1, 128>>>();
    k_seqlen<<<BB, 128>>>(tokens, out + LOGITS_N);

    dim3 gx(TT, 32);
    k_xg<<<gx, 128, 196608>>>(tokens, emb, Wxf, bf, Wxb, bb);

    // PROBE: 128-step recurrence on separate counters; writes a prefix of g_h
    // that the full run below recomputes identically. Exists purely to measure
    // per-step cost of the recurrence via dur_R7 - dur_R6.
    k_recur_t<128,64><<<128, 128, 98304>>>(Whf, Whb);

    k_recur_t<512,0><<<128, 128, 98304>>>(Whf, Whb);

    k_dense<<<TT, 576, 149504>>>(Wd, bd, out);

    k_crf<<<BB, 32>>>(labels, trans, out, out + LOGITS_N + BB);
}

// round 8
// speedup vs baseline: 1.6045x; 1.6045x over previous
#include <cuda_runtime.h>
#include <cstdint>
#include <cstddef>

#define BB 64
#define TT 512
#define EE 256
#define HH 256
#define LLB 9
#define G4 1024   // 4*H

typedef unsigned long long u64;

// Scratch (device globals; no allocations allowed)
__device__ float g_xg[(size_t)2*TT*G4*BB];   // [dir][t][col][b] 256 MiB
__device__ float g_h [(size_t)2*TT*HH*BB];   // [dir][t][u][b]    64 MiB
__device__ int      g_seqlen[BB];
__device__ unsigned g_barc[64];   // [0] fwd, [32] bwd (separate 128B lines)

// ---------------- f32x2 helpers ----------------
__device__ __forceinline__ u64 pk2(float x, float y){
    u64 r; asm("mov.b64 %0,{%1,%2};" : "=l"(r) : "f"(x), "f"(y)); return r;
}
__device__ __forceinline__ void upk2(u64 v, float& x, float& y){
    asm("mov.b64 {%0,%1},%2;" : "=f"(x), "=f"(y) : "l"(v));
}
__device__ __forceinline__ u64 fma2(u64 a, u64 b, u64 c){
    u64 d; asm("fma.rn.f32x2 %0,%1,%2,%3;" : "=l"(d) : "l"(a), "l"(b), "l"(c)); return d;
}
__device__ __forceinline__ u64 add2(u64 a, u64 b){
    u64 d; asm("add.rn.f32x2 %0,%1,%2;" : "=l"(d) : "l"(a), "l"(b)); return d;
}

// ---------------- release/acquire barrier primitives ----------------
__device__ __forceinline__ void red_release_add1(unsigned* p){
    asm volatile("red.release.gpu.add.u32 [%0],1;" :: "l"(p) : "memory");
}
__device__ __forceinline__ unsigned ld_acquire(const unsigned* p){
    unsigned v; asm volatile("ld.acquire.gpu.u32 %0,[%1];" : "=r"(v) : "l"(p) : "memory");
    return v;
}

__device__ __forceinline__ float sigf(float x){
    return __fdividef(1.f, 1.f + __expf(-x));
}
__device__ __forceinline__ float tanhfast(float x){
    return 1.f - __fdividef(2.f, __expf(2.f*x) + 1.f);
}

// ---------------------------------------------------------------- seq_len
__global__ void k_seqlen(const int* __restrict__ tokens, float* __restrict__ out_seq){
    int b = blockIdx.x, tid = threadIdx.x;
    int cnt = 0;
    for (int t = tid; t < TT; t += blockDim.x)
        cnt += (tokens[b*TT + t] != 0);
    __shared__ int sred[128];
    sred[tid] = cnt; __syncthreads();
    for (int s = 64; s > 0; s >>= 1){
        if (tid < s) sred[tid] += sred[tid+s];
        __syncthreads();
    }
    if (tid == 0){ g_seqlen[b] = sred[0]; out_seq[b] = (float)sred[0]; }
}

__global__ void k_init(){
    if (threadIdx.x < 64) g_barc[threadIdx.x] = 0u;
}

// ---------------------------------------------------------------- xg GEMM
// g_xg[t, col, b] = emb[tokens[b,t]] @ Wx + bias.
// 256 threads (2 warps/SMSP). Thread = 4 cols x 4 batches.
// Per warp per k: 1 LDS.128 A (2 phases) + 2 LDS.128 Wdup (broadcast) + 8 fma2.
__global__ void __launch_bounds__(256) k_xg(
    const int* __restrict__ tokens, const float* __restrict__ emb,
    const float* __restrict__ Wxf, const float* __restrict__ bf,
    const float* __restrict__ Wxb, const float* __restrict__ bb_)
{
    extern __shared__ float smf[];
    float* As = smf;                   // [256 k][64 b]        64KB
    u64*   Wd = (u64*)(smf + 16384);   // [256 k][64 c] dup   128KB
    __shared__ int toks[64];

    int t    = blockIdx.x;
    int ct   = blockIdx.y;
    int dir  = ct >> 4;
    int col0 = (ct & 15) * 64;
    const float* Wx   = dir ? Wxb : Wxf;
    const float* bias = dir ? bb_ : bf;
    int tid  = threadIdx.x;
    int w    = tid >> 5, lane = tid & 31;
    int half = lane >> 4, bq = lane & 15;
    int cq   = w*2 + half;             // col-quad 0..15 (4 cols each)

    if (tid < 64) toks[tid] = tokens[tid*TT + t];
    __syncthreads();

    for (int i = tid; i < 4096; i += 256){
        int k4 = i >> 6, b = i & 63;
        float4 v = *(const float4*)(emb + (size_t)toks[b]*EE + k4*4);
        As[(4*k4+0)*64 + b] = v.x;
        As[(4*k4+1)*64 + b] = v.y;
        As[(4*k4+2)*64 + b] = v.z;
        As[(4*k4+3)*64 + b] = v.w;
    }
    for (int i = tid; i < 4096; i += 256){
        int k = i >> 4, q = i & 15;
        float4 v = *(const float4*)(Wx + (size_t)k*G4 + col0 + q*4);
        Wd[k*64 + q*4 + 0] = pk2(v.x, v.x);
        Wd[k*64 + q*4 + 1] = pk2(v.y, v.y);
        Wd[k*64 + q*4 + 2] = pk2(v.z, v.z);
        Wd[k*64 + q*4 + 3] = pk2(v.w, v.w);
    }
    __syncthreads();

    u64 acc[4][2];
    #pragma unroll
    for (int j = 0; j < 4; ++j){
        float bv = bias[col0 + 4*cq + j];
        acc[j][0] = pk2(bv, bv);
        acc[j][1] = acc[j][0];
    }

    #pragma unroll 8
    for (int k = 0; k < 256; ++k){
        ulonglong2 a  = *(const ulonglong2*)(As + k*64 + 4*bq);    // (b0b1),(b2b3)
        ulonglong2 wA = *(const ulonglong2*)(Wd + k*64 + 4*cq);    // dup c0,c1
        ulonglong2 wB = *(const ulonglong2*)(Wd + k*64 + 4*cq + 2);// dup c2,c3
        acc[0][0]=fma2(a.x,wA.x,acc[0][0]); acc[0][1]=fma2(a.y,wA.x,acc[0][1]);
        acc[1][0]=fma2(a.x,wA.y,acc[1][0]); acc[1][1]=fma2(a.y,wA.y,acc[1][1]);
        acc[2][0]=fma2(a.x,wB.x,acc[2][0]); acc[2][1]=fma2(a.y,wB.x,acc[2][1]);
        acc[3][0]=fma2(a.x,wB.y,acc[3][0]); acc[3][1]=fma2(a.y,wB.y,acc[3][1]);
    }

    float* dst = g_xg + ((size_t)(dir*TT + t)*G4 + col0 + 4*cq)*64 + 4*bq;
    #pragma unroll
    for (int j = 0; j < 4; ++j){
        ulonglong2 v; v.x = acc[j][0]; v.y = acc[j][1];
        *(ulonglong2*)(dst + (size_t)j*64) = v;
    }
}

// ---------------------------------------------------------------- recurrence
// 128 CTAs: [0,64) fwd, [64,128) bwd. CTA = 4 units x 64 batches.
// 512 threads = 4 k-quarters x 4 units x 32 batch-pairs (4 warps/SMSP).
// Warp = single (kq, ul), 32 bp: per k: 1 LDS.64 h (2 phases) + 2 LDS.128 w
// (broadcast) + 4 fma2. Partials reduced through smem by kq=0.
template<int NSTEPS>
__global__ void __launch_bounds__(512) k_recur_t(
    const float* __restrict__ Whf, const float* __restrict__ Whb)
{
    extern __shared__ u64 smu[];
    u64* hs  = smu;            // [256 k][32 bp]           64KB
    u64* wd  = smu + 8192;     // [256 k][4 ul][4 g] dup   32KB
    u64* red = smu + 12288;    // [3 kq][128 r][4 g]       12KB

    int cta = blockIdx.x;
    int dir = cta >> 6;
    int u0  = (cta & 63) * 4;
    const float* Wh = dir ? Whb : Whf;
    int tid = threadIdx.x;
    int kq  = tid >> 7;        // 0..3
    int r   = tid & 127;
    int ul  = r >> 5, bp = r & 31;
    int u   = u0 + ul;
    int k0  = kq * 64;

    for (int i = tid; i < 4096; i += 512){
        int k = i >> 4, q = i & 15;
        int ulx = q >> 2, g = q & 3;
        float v = Wh[(size_t)k*G4 + g*HH + u0 + ulx];
        wd[k*16 + ulx*4 + g] = pk2(v, v);
    }
    __syncthreads();

    float ca = 0.f, cb = 0.f;
    float* hF = g_h + (size_t)dir * TT * HH * BB;
    const u64* xg = (const u64*)g_xg;
    unsigned* barp = &g_barc[dir*32];
    const u64* wrow0 = wd + ul*4 + k0*16;
    const u64* hrow0 = hs + k0*32 + bp;

    u64 x0 = 0, x1 = 0, x2 = 0, x3 = 0;
    int t0 = dir ? (TT-1) : 0;
    if (kq == 0){
        size_t xb = ((size_t)(dir*TT + t0)*G4 + u)*32 + bp;
        x0 = xg[xb];
        x1 = xg[xb +  8192];
        x2 = xg[xb + 16384];
        x3 = xg[xb + 24576];
    }

    for (int step = 0; step < NSTEPS; ++step){
        int t = dir ? (TT-1-step) : step;
        u64 a0 = x0, a1 = x1, a2 = x2, a3 = x3;   // zeros for kq>0

        if (step > 0){
            if (tid == 0){
                unsigned need = 64u * (unsigned)step;
                while (ld_acquire(barp) < need) __nanosleep(32);
            }
            __syncthreads();

            int tp = dir ? (t+1) : (t-1);
            const ulonglong2* src = (const ulonglong2*)(hF + (size_t)tp*HH*BB);
            ulonglong2* dsts = (ulonglong2*)hs;
            #pragma unroll
            for (int i = 0; i < 8; ++i) dsts[tid + 512*i] = src[tid + 512*i];
            __syncthreads();

            #pragma unroll 8
            for (int kk = 0; kk < 64; ++kk){
                u64 h2 = hrow0[kk*32];
                ulonglong2 w01 = *(const ulonglong2*)(wrow0 + kk*16);
                ulonglong2 w23 = *(const ulonglong2*)(wrow0 + kk*16 + 2);
                a0 = fma2(h2, w01.x, a0);
                a1 = fma2(h2, w01.y, a1);
                a2 = fma2(h2, w23.x, a2);
                a3 = fma2(h2, w23.y, a3);
            }

            if (kq > 0){
                u64* rp = red + ((kq-1)*128 + r)*4;
                rp[0] = a0; rp[1] = a1; rp[2] = a2; rp[3] = a3;
            }
            __syncthreads();
            if (kq == 0){
                #pragma unroll
                for (int q = 0; q < 3; ++q){
                    const u64* rp = red + (q*128 + r)*4;
                    a0 = add2(a0, rp[0]);
                    a1 = add2(a1, rp[1]);
                    a2 = add2(a2, rp[2]);
                    a3 = add2(a3, rp[3]);
                }
            }
        }

        if (kq == 0){
            float ia, ib, fa, fb, ga, gb, oa, ob;
            upk2(a0, ia, ib);
            upk2(a1, fa, fb);
            upk2(a2, ga, gb);
            upk2(a3, oa, ob);
            ca = sigf(fa)*ca + sigf(ia)*tanhfast(ga);
            cb = sigf(fb)*cb + sigf(ib)*tanhfast(gb);
            float ha = sigf(oa)*tanhfast(ca);
            float hb = sigf(ob)*tanhfast(cb);
            *(u64*)(hF + (size_t)t*HH*BB + (size_t)u*BB + 2*bp) = pk2(ha, hb);
        }

        __syncthreads();                 // h stores of this CTA done
        if (tid == 0) red_release_add1(barp);

        if (kq == 0 && step + 1 < NSTEPS){
            int tn = dir ? (t-1) : (t+1);
            size_t xn = ((size_t)(dir*TT + tn)*G4 + u)*32 + bp;
            x0 = xg[xn];
            x1 = xg[xn +  8192];
            x2 = xg[xn + 16384];
            x3 = xg[xn + 24576];
        }
    }
}

// ---------------------------------------------------------------- dense
__global__ void __launch_bounds__(576) k_dense(
    const float* __restrict__ Wd, const float* __restrict__ bd,
    float* __restrict__ out)
{
    extern __shared__ float sm[];
    float* hsf = sm;
    float* Wds = sm + 32768;

    int t = blockIdx.x, tid = threadIdx.x;
    const float4* s0 = (const float4*)(g_h + (size_t)t*HH*BB);
    const float4* s1 = (const float4*)(g_h + (size_t)(TT + t)*HH*BB);
    float4* d0 = (float4*)hsf;
    for (int i = tid; i < 4096; i += 576) d0[i] = s0[i];
    for (int i = tid; i < 4096; i += 576) d0[4096 + i] = s1[i];
    for (int i = tid; i < 512*LLB; i += 576) Wds[i] = Wd[i];
    __syncthreads();

    int b = tid / LLB;
    int l = tid - b*LLB;
    float acc = bd[l];
    #pragma unroll 4
    for (int k = 0; k < 256; ++k)
        acc += hsf[k*64 + b] * Wds[k*LLB + l];
    #pragma unroll 4
    for (int k = 0; k < 256; ++k)
        acc += hsf[16384 + k*64 + b] * Wds[(256+k)*LLB + l];
    out[((size_t)b*TT + t)*LLB + l] = acc;
}

// ---------------------------------------------------------------- CRF
__global__ void k_crf(const int* __restrict__ labels, const float* __restrict__ trans,
                      const float* __restrict__ logits, float* __restrict__ out_ll)
{
    int b = blockIdx.x;
    int j = threadIdx.x;
    int sl = g_seqlen[b];
    const float* lg = logits + (size_t)b*TT*LLB;
    const int*   tg = labels + (size_t)b*TT;

    float sc = 0.f;
    for (int t = j; t < TT; t += 32){
        if (t < sl){
            sc += lg[t*LLB + tg[t]];
            if (t >= 1) sc += trans[tg[t-1]*LLB + tg[t]];
        }
    }
    #pragma unroll
    for (int o = 16; o > 0; o >>= 1) sc += __shfl_xor_sync(0xffffffffu, sc, o);

    float trj[9];
    if (j < 9){
        #pragma unroll
        for (int i = 0; i < 9; ++i) trj[i] = trans[i*LLB + j];
    }
    float a[9];
    #pragma unroll
    for (int i = 0; i < 9; ++i) a[i] = lg[i];

    __shared__ float sa[9];
    int tmax = (sl < TT) ? sl : TT;
    for (int t = 1; t < tmax; ++t){
        if (j < 9){
            float lgt = lg[t*LLB + j];
            float v[9]; float m = -1e30f;
            #pragma unroll
            for (int i = 0; i < 9; ++i){ v[i] = a[i] + trj[i]; m = fmaxf(m, v[i]); }
            float s = 0.f;
            #pragma unroll
            for (int i = 0; i < 9; ++i) s += __expf(v[i] - m);
            sa[j] = m + __logf(s) + lgt;
        }
        __syncwarp();
        #pragma unroll
        for (int i = 0; i < 9; ++i) a[i] = sa[i];
        __syncwarp();
    }

    if (j == 0){
        float m = a[0];
        #pragma unroll
        for (int i = 1; i < 9; ++i) m = fmaxf(m, a[i]);
        float s = 0.f;
        #pragma unroll
        for (int i = 0; i < 9; ++i) s += __expf(a[i] - m);
        out_ll[b] = sc - (m + __logf(s));
    }
}

// ---------------------------------------------------------------- launch
extern "C" void kernel_launch(void* const* d_in, const int* in_sizes, int n_in,
                              void* d_out, int out_size)
{
    const int*   tokens = (const int*)  d_in[0];
    const int*   labels = (const int*)  d_in[1];
    const float* emb    = (const float*)d_in[2];
    const float* Wxf    = (const float*)d_in[3];
    const float* Whf    = (const float*)d_in[4];
    const float* bf     = (const float*)d_in[5];
    const float* Wxb    = (const float*)d_in[6];
    const float* Whb    = (const float*)d_in[7];
    const float* bb     = (const float*)d_in[8];
    const float* Wd     = (const float*)d_in[9];
    const float* bd     = (const float*)d_in[10];
    const float* trans  = (const float*)d_in[11];
    float* out = (float*)d_out;

    cudaFuncSetAttribute(k_xg, cudaFuncAttributeMaxDynamicSharedMemorySize, 196608);
    cudaFuncSetAttribute(k_recur_t<512>, cudaFuncAttributeMaxDynamicSharedMemorySize, 110592);
    cudaFuncSetAttribute(k_dense, cudaFuncAttributeMaxDynamicSharedMemorySize, 149504);

    const int LOGITS_N = BB*TT*LLB;   // 294912

    k_init<<<1, 64>>>();
    k_seqlen<<<BB, 128>>>(tokens, out + LOGITS_N);

    dim3 gx(TT, 32);
    k_xg<<<gx, 256, 196608>>>(tokens, emb, Wxf, bf, Wxb, bb);

    // launch #4 -> ncu-profiled slot
    k_recur_t<512><<<128, 512, 110592>>>(Whf, Whb);

    k_dense<<<TT, 576, 149504>>>(Wd, bd, out);

    k_crf<<<BB, 32>>>(labels, trans, out, out + LOGITS_N + BB);
}

// round 10
// speedup vs baseline: 1.7669x; 1.1012x over previous
#include <cuda_runtime.h>
#include <cstdint>
#include <cstddef>

#define BB 64
#define TT 512
#define EE 256
#define HH 256
#define LLB 9
#define G4 1024   // 4*H

typedef unsigned long long u64;

// Scratch (device globals; no allocations allowed)
__device__ float g_xg[(size_t)2*TT*G4*BB];   // [dir][t][col][b] 256 MiB
__device__ float g_h [(size_t)2*TT*HH*BB];   // [dir][t][u][b]    64 MiB
__device__ int      g_seqlen[BB];
__device__ unsigned g_barc[64];   // [0] fwd, [32] bwd (separate 128B lines)

// ---------------- f32x2 helpers ----------------
__device__ __forceinline__ u64 pk2(float x, float y){
    u64 r; asm("mov.b64 %0,{%1,%2};" : "=l"(r) : "f"(x), "f"(y)); return r;
}
__device__ __forceinline__ void upk2(u64 v, float& x, float& y){
    asm("mov.b64 {%0,%1},%2;" : "=f"(x), "=f"(y) : "l"(v));
}
__device__ __forceinline__ u64 fma2(u64 a, u64 b, u64 c){
    u64 d; asm("fma.rn.f32x2 %0,%1,%2,%3;" : "=l"(d) : "l"(a), "l"(b), "l"(c)); return d;
}
__device__ __forceinline__ u64 add2(u64 a, u64 b){
    u64 d; asm("add.rn.f32x2 %0,%1,%2;" : "=l"(d) : "l"(a), "l"(b)); return d;
}

// ---------------- release/acquire barrier primitives ----------------
__device__ __forceinline__ void red_release_add1(unsigned* p){
    asm volatile("red.release.gpu.add.u32 [%0],1;" :: "l"(p) : "memory");
}
__device__ __forceinline__ unsigned ld_acquire(const unsigned* p){
    unsigned v; asm volatile("ld.acquire.gpu.u32 %0,[%1];" : "=r"(v) : "l"(p) : "memory");
    return v;
}

__device__ __forceinline__ float sigf(float x){
    return __fdividef(1.f, 1.f + __expf(-x));
}
__device__ __forceinline__ float tanhfast(float x){
    return 1.f - __fdividef(2.f, __expf(2.f*x) + 1.f);
}

// ---------------------------------------------------------------- seq_len
__global__ void k_seqlen(const int* __restrict__ tokens, float* __restrict__ out_seq){
    int b = blockIdx.x, tid = threadIdx.x;
    int cnt = 0;
    for (int t = tid; t < TT; t += blockDim.x)
        cnt += (tokens[b*TT + t] != 0);
    __shared__ int sred[128];
    sred[tid] = cnt; __syncthreads();
    for (int s = 64; s > 0; s >>= 1){
        if (tid < s) sred[tid] += sred[tid+s];
        __syncthreads();
    }
    if (tid == 0){ g_seqlen[b] = sred[0]; out_seq[b] = (float)sred[0]; }
}

__global__ void k_init(){
    if (threadIdx.x < 64) g_barc[threadIdx.x] = 0u;
}

// ---------------------------------------------------------------- xg GEMM (persistent, W-stationary)
// 128 CTAs x 256 threads. CTA owns (dir, 64-col tile) and 128 timesteps.
// W loaded+duplicated ONCE. Per t: FULL emb rows register-prefetched
// (4 threads/batch x 16 float4 = all 64 k4 rows), then smem gather, then
// main loop: warp = 32 cols x 16 batches, thread = 2 cols x 8 batches.
__global__ void __launch_bounds__(256) k_xg(
    const int* __restrict__ tokens, const float* __restrict__ emb,
    const float* __restrict__ Wxf, const float* __restrict__ bf,
    const float* __restrict__ Wxb, const float* __restrict__ bb_)
{
    extern __shared__ float smf[];
    float* As = smf;                   // [256 k][64 b] f32    64KB
    u64*   Wd = (u64*)(smf + 16384);   // [256 k][64 c] dup   128KB

    int cta  = blockIdx.x;
    int ct   = cta & 31;
    int tch  = cta >> 5;               // 0..3 -> 128 t each
    int dir  = ct >> 4;
    int col0 = (ct & 15) * 64;
    const float* Wx   = dir ? Wxb : Wxf;
    const float* bias = dir ? bb_ : bf;
    int tid  = threadIdx.x;
    int w    = tid >> 5, lane = tid & 31;
    int cp   = lane & 15, bh = lane >> 4;
    int cg   = w & 1, bg = w >> 1;
    int pb   = bg*8 + bh*4;            // 4 batch-pairs base
    int cb   = cg*32 + cp*2;           // 2 cols base

    // W load + duplicate, once
    for (int i = tid; i < 4096; i += 256){
        int k = i >> 4, q = i & 15;
        float4 v = *(const float4*)(Wx + (size_t)k*G4 + col0 + q*4);
        Wd[k*64 + q*4 + 0] = pk2(v.x, v.x);
        Wd[k*64 + q*4 + 1] = pk2(v.y, v.y);
        Wd[k*64 + q*4 + 2] = pk2(v.z, v.z);
        Wd[k*64 + q*4 + 3] = pk2(v.w, v.w);
    }
    float bv0 = bias[col0 + cb], bv1 = bias[col0 + cb + 1];
    u64 bini0 = pk2(bv0, bv0), bini1 = pk2(bv1, bv1);

    int gb   = tid & 63;       // batch this thread gathers
    int gk16 = (tid >> 6)*16;  // this thread's float4-row base: 16 rows

    int tbase = tch * 128;
    float4 pf[16];
    {
        int tok = tokens[gb*TT + tbase];
        const float4* row = (const float4*)(emb + (size_t)tok*EE);
        #pragma unroll
        for (int j = 0; j < 16; ++j) pf[j] = row[gk16 + j];
    }

    for (int i = 0; i < 128; ++i){
        int t = tbase + i;
        __syncthreads();   // As free (previous compute done); W ready (i==0)
        #pragma unroll
        for (int j = 0; j < 16; ++j){
            int k4 = gk16 + j;
            As[(4*k4+0)*64+gb]=pf[j].x;
            As[(4*k4+1)*64+gb]=pf[j].y;
            As[(4*k4+2)*64+gb]=pf[j].z;
            As[(4*k4+3)*64+gb]=pf[j].w;
        }
        __syncthreads();

        if (i + 1 < 128){   // prefetch next t's emb rows (hidden under compute)
            int tok = tokens[gb*TT + t + 1];
            const float4* row = (const float4*)(emb + (size_t)tok*EE);
            #pragma unroll
            for (int j = 0; j < 16; ++j) pf[j] = row[gk16 + j];
        }

        u64 acc00 = bini0, acc01 = bini0, acc02 = bini0, acc03 = bini0;
        u64 acc10 = bini1, acc11 = bini1, acc12 = bini1, acc13 = bini1;
        const u64* Asu = (const u64*)As;

        #pragma unroll 8
        for (int k = 0; k < 256; ++k){
            ulonglong2 a01 = *(const ulonglong2*)(Asu + k*32 + pb);      // bpairs pb,pb+1
            ulonglong2 a23 = *(const ulonglong2*)(Asu + k*32 + pb + 2);  // bpairs pb+2,pb+3
            ulonglong2 wv  = *(const ulonglong2*)(Wd  + k*64 + cb);      // dup cols cb,cb+1
            acc00 = fma2(a01.x, wv.x, acc00);
            acc01 = fma2(a01.y, wv.x, acc01);
            acc02 = fma2(a23.x, wv.x, acc02);
            acc03 = fma2(a23.y, wv.x, acc03);
            acc10 = fma2(a01.x, wv.y, acc10);
            acc11 = fma2(a01.y, wv.y, acc11);
            acc12 = fma2(a23.x, wv.y, acc12);
            acc13 = fma2(a23.y, wv.y, acc13);
        }

        u64* dst = (u64*)g_xg + ((size_t)(dir*TT + t)*G4 + col0 + cb)*32 + pb;
        ulonglong2 s;
        s.x = acc00; s.y = acc01; *(ulonglong2*)(dst)          = s;
        s.x = acc02; s.y = acc03; *(ulonglong2*)(dst + 2)      = s;
        s.x = acc10; s.y = acc11; *(ulonglong2*)(dst + 32)     = s;
        s.x = acc12; s.y = acc13; *(ulonglong2*)(dst + 32 + 2) = s;
    }
}

// ---------------------------------------------------------------- recurrence (IDENTICAL to R8)
// 128 CTAs: [0,64) fwd, [64,128) bwd. CTA = 4 units x 64 batches.
// 512 threads = 4 k-quarters x 4 units x 32 batch-pairs (4 warps/SMSP).
template<int NSTEPS>
__global__ void __launch_bounds__(512) k_recur_t(
    const float* __restrict__ Whf, const float* __restrict__ Whb)
{
    extern __shared__ u64 smu[];
    u64* hs  = smu;            // [256 k][32 bp]           64KB
    u64* wd  = smu + 8192;     // [256 k][4 ul][4 g] dup   32KB
    u64* red = smu + 12288;    // [3 kq][128 r][4 g]       12KB

    int cta = blockIdx.x;
    int dir = cta >> 6;
    int u0  = (cta & 63) * 4;
    const float* Wh = dir ? Whb : Whf;
    int tid = threadIdx.x;
    int kq  = tid >> 7;
    int r   = tid & 127;
    int ul  = r >> 5, bp = r & 31;
    int u   = u0 + ul;
    int k0  = kq * 64;

    for (int i = tid; i < 4096; i += 512){
        int k = i >> 4, q = i & 15;
        int ulx = q >> 2, g = q & 3;
        float v = Wh[(size_t)k*G4 + g*HH + u0 + ulx];
        wd[k*16 + ulx*4 + g] = pk2(v, v);
    }
    __syncthreads();

    float ca = 0.f, cb = 0.f;
    float* hF = g_h + (size_t)dir * TT * HH * BB;
    const u64* xg = (const u64*)g_xg;
    unsigned* barp = &g_barc[dir*32];
    const u64* wrow0 = wd + ul*4 + k0*16;
    const u64* hrow0 = hs + k0*32 + bp;

    u64 x0 = 0, x1 = 0, x2 = 0, x3 = 0;
    int t0 = dir ? (TT-1) : 0;
    if (kq == 0){
        size_t xb = ((size_t)(dir*TT + t0)*G4 + u)*32 + bp;
        x0 = xg[xb];
        x1 = xg[xb +  8192];
        x2 = xg[xb + 16384];
        x3 = xg[xb + 24576];
    }

    for (int step = 0; step < NSTEPS; ++step){
        int t = dir ? (TT-1-step) : step;
        u64 a0 = x0, a1 = x1, a2 = x2, a3 = x3;

        if (step > 0){
            if (tid == 0){
                unsigned need = 64u * (unsigned)step;
                while (ld_acquire(barp) < need) __nanosleep(32);
            }
            __syncthreads();

            int tp = dir ? (t+1) : (t-1);
            const ulonglong2* src = (const ulonglong2*)(hF + (size_t)tp*HH*BB);
            ulonglong2* dsts = (ulonglong2*)hs;
            #pragma unroll
            for (int i = 0; i < 8; ++i) dsts[tid + 512*i] = src[tid + 512*i];
            __syncthreads();

            #pragma unroll 8
            for (int kk = 0; kk < 64; ++kk){
                u64 h2 = hrow0[kk*32];
                ulonglong2 w01 = *(const ulonglong2*)(wrow0 + kk*16);
                ulonglong2 w23 = *(const ulonglong2*)(wrow0 + kk*16 + 2);
                a0 = fma2(h2, w01.x, a0);
                a1 = fma2(h2, w01.y, a1);
                a2 = fma2(h2, w23.x, a2);
                a3 = fma2(h2, w23.y, a3);
            }

            if (kq > 0){
                u64* rp = red + ((kq-1)*128 + r)*4;
                rp[0] = a0; rp[1] = a1; rp[2] = a2; rp[3] = a3;
            }
            __syncthreads();
            if (kq == 0){
                #pragma unroll
                for (int q = 0; q < 3; ++q){
                    const u64* rp = red + (q*128 + r)*4;
                    a0 = add2(a0, rp[0]);
                    a1 = add2(a1, rp[1]);
                    a2 = add2(a2, rp[2]);
                    a3 = add2(a3, rp[3]);
                }
            }
        }

        if (kq == 0){
            float ia, ib, fa, fb, ga, gb, oa, ob;
            upk2(a0, ia, ib);
            upk2(a1, fa, fb);
            upk2(a2, ga, gb);
            upk2(a3, oa, ob);
            ca = sigf(fa)*ca + sigf(ia)*tanhfast(ga);
            cb = sigf(fb)*cb + sigf(ib)*tanhfast(gb);
            float ha = sigf(oa)*tanhfast(ca);
            float hb = sigf(ob)*tanhfast(cb);
            *(u64*)(hF + (size_t)t*HH*BB + (size_t)u*BB + 2*bp) = pk2(ha, hb);
        }

        __syncthreads();
        if (tid == 0) red_release_add1(barp);

        if (kq == 0 && step + 1 < NSTEPS){
            int tn = dir ? (t-1) : (t+1);
            size_t xn = ((size_t)(dir*TT + tn)*G4 + u)*32 + bp;
            x0 = xg[xn];
            x1 = xg[xn +  8192];
            x2 = xg[xn + 16384];
            x3 = xg[xn + 24576];
        }
    }
}

// ---------------------------------------------------------------- dense
__global__ void __launch_bounds__(576) k_dense(
    const float* __restrict__ Wd, const float* __restrict__ bd,
    float* __restrict__ out)
{
    extern __shared__ float sm[];
    float* hsf = sm;
    float* Wds = sm + 32768;

    int t = blockIdx.x, tid = threadIdx.x;
    const float4* s0 = (const float4*)(g_h + (size_t)t*HH*BB);
    const float4* s1 = (const float4*)(g_h + (size_t)(TT + t)*HH*BB);
    float4* d0 = (float4*)hsf;
    for (int i = tid; i < 4096; i += 576) d0[i] = s0[i];
    for (int i = tid; i < 4096; i += 576) d0[4096 + i] = s1[i];
    for (int i = tid; i < 512*LLB; i += 576) Wds[i] = Wd[i];
    __syncthreads();

    int b = tid / LLB;
    int l = tid - b*LLB;
    float acc = bd[l];
    #pragma unroll 4
    for (int k = 0; k < 256; ++k)
        acc += hsf[k*64 + b] * Wds[k*LLB + l];
    #pragma unroll 4
    for (int k = 0; k < 256; ++k)
        acc += hsf[16384 + k*64 + b] * Wds[(256+k)*LLB + l];
    out[((size_t)b*TT + t)*LLB + l] = acc;
}

// ---------------------------------------------------------------- CRF
__global__ void k_crf(const int* __restrict__ labels, const float* __restrict__ trans,
                      const float* __restrict__ logits, float* __restrict__ out_ll)
{
    int b = blockIdx.x;
    int j = threadIdx.x;
    int sl = g_seqlen[b];
    const float* lg = logits + (size_t)b*TT*LLB;
    const int*   tg = labels + (size_t)b*TT;

    float sc = 0.f;
    for (int t = j; t < TT; t += 32){
        if (t < sl){
            sc += lg[t*LLB + tg[t]];
            if (t >= 1) sc += trans[tg[t-1]*LLB + tg[t]];
        }
    }
    #pragma unroll
    for (int o = 16; o > 0; o >>= 1) sc += __shfl_xor_sync(0xffffffffu, sc, o);

    float trj[9];
    if (j < 9){
        #pragma unroll
        for (int i = 0; i < 9; ++i) trj[i] = trans[i*LLB + j];
    }
    float a[9];
    #pragma unroll
    for (int i = 0; i < 9; ++i) a[i] = lg[i];

    __shared__ float sa[9];
    int tmax = (sl < TT) ? sl : TT;
    for (int t = 1; t < tmax; ++t){
        if (j < 9){
            float lgt = lg[t*LLB + j];
            float v[9]; float m = -1e30f;
            #pragma unroll
            for (int i = 0; i < 9; ++i){ v[i] = a[i] + trj[i]; m = fmaxf(m, v[i]); }
            float s = 0.f;
            #pragma unroll
            for (int i = 0; i < 9; ++i) s += __expf(v[i] - m);
            sa[j] = m + __logf(s) + lgt;
        }
        __syncwarp();
        #pragma unroll
        for (int i = 0; i < 9; ++i) a[i] = sa[i];
        __syncwarp();
    }

    if (j == 0){
        float m = a[0];
        #pragma unroll
        for (int i = 1; i < 9; ++i) m = fmaxf(m, a[i]);
        float s = 0.f;
        #pragma unroll
        for (int i = 0; i < 9; ++i) s += __expf(a[i] - m);
        out_ll[b] = sc - (m + __logf(s));
    }
}

// ---------------------------------------------------------------- launch
extern "C" void kernel_launch(void* const* d_in, const int* in_sizes, int n_in,
                              void* d_out, int out_size)
{
    const int*   tokens = (const int*)  d_in[0];
    const int*   labels = (const int*)  d_in[1];
    const float* emb    = (const float*)d_in[2];
    const float* Wxf    = (const float*)d_in[3];
    const float* Whf    = (const float*)d_in[4];
    const float* bf     = (const float*)d_in[5];
    const float* Wxb    = (const float*)d_in[6];
    const float* Whb    = (const float*)d_in[7];
    const float* bb     = (const float*)d_in[8];
    const float* Wd     = (const float*)d_in[9];
    const float* bd     = (const float*)d_in[10];
    const float* trans  = (const float*)d_in[11];
    float* out = (float*)d_out;

    cudaFuncSetAttribute(k_xg, cudaFuncAttributeMaxDynamicSharedMemorySize, 196608);
    cudaFuncSetAttribute(k_recur_t<512>, cudaFuncAttributeMaxDynamicSharedMemorySize, 110592);
    cudaFuncSetAttribute(k_dense, cudaFuncAttributeMaxDynamicSharedMemorySize, 149504);

    const int LOGITS_N = BB*TT*LLB;   // 294912

    k_init<<<1, 64>>>();
    k_seqlen<<<BB, 128>>>(tokens, out + LOGITS_N);

    k_xg<<<128, 256, 196608>>>(tokens, emb, Wxf, bf, Wxb, bb);

    // launch #4 -> ncu-profiled slot
    k_recur_t<512><<<128, 512, 110592>>>(Whf, Whb);

    k_dense<<<TT, 576, 149504>>>(Wd, bd, out);

    k_crf<<<BB, 32>>>(labels, trans, out, out + LOGITS_N + BB);
}